// round 1
// baseline (speedup 1.0000x reference)
#include <cuda_runtime.h>
#include <cstdint>

#define DD 64
#define MAXN 50000

// scratch (static __device__ — no allocations allowed)
__device__ float g_agg[MAXN * DD];
__device__ float g_P[MAXN * DD];
__device__ float g_Q[MAXN * DD];
__device__ int   g_is64;

// ---------------------------------------------------------------------------
// Probe: edge_index may be int64 (as written in reference) or int32 (JAX x64
// disabled demotes silently). int64 layout with indices < 50000 has every odd
// 32-bit word == 0; int32 layout essentially never has 16 consecutive zeros.
// ---------------------------------------------------------------------------
__global__ void k_detect(const int* __restrict__ ei) {
    if (threadIdx.x == 0 && blockIdx.x == 0) {
        int z = 0;
#pragma unroll
        for (int k = 1; k < 32; k += 2) z |= ei[k];
        g_is64 = (z == 0) ? 1 : 0;
    }
}

__device__ __forceinline__ long long edge_at(const void* ei, long long i) {
    if (g_is64) return ((const long long*)ei)[i];
    return (long long)((const int*)ei)[i];
}

// ---------------------------------------------------------------------------
// Zero agg
// ---------------------------------------------------------------------------
__global__ void k_zero(int n4) {
    int i = blockIdx.x * blockDim.x + threadIdx.x;
    if (i < n4) ((float4*)g_agg)[i] = make_float4(0.f, 0.f, 0.f, 0.f);
}

// ---------------------------------------------------------------------------
// Scatter: agg[dst] += x[src], vectorized float4 atomics.
// One warp handles 2 edges: lanes 0-15 -> edge a, lanes 16-31 -> edge b;
// the 16 lanes of a half-warp cover the 64-float row as 16 float4 chunks
// (fully coalesced 256B row reads, x is L2-resident at 12.8MB).
// ---------------------------------------------------------------------------
__global__ void k_scatter(const float* __restrict__ x, const void* __restrict__ ei, int E) {
    int t = blockIdx.x * blockDim.x + threadIdx.x;
    int warp = t >> 5;
    int lane = t & 31;
    long long e = (long long)warp * 2 + (lane >> 4);
    int sub = lane & 15;
    if (e >= E) return;
    long long src = edge_at(ei, e);
    long long dst = edge_at(ei, (long long)E + e);
    float4 v = ((const float4*)x)[src * 16 + sub];
    atomicAdd(((float4*)g_agg) + (dst * 16 + sub), v);   // sm_90+ vector RED
}

// ---------------------------------------------------------------------------
// Node kernel: per node n:
//   in  = x[n] + agg[n]
//   emb = relu(in @ W_enc + b_enc)
//   P[n] = emb @ W1a   (W1 rows 0..63)
//   Q[n] = emb @ W1b   (W1 rows 64..127)
// One thread per node. Weights in shared (broadcast LDS.128), 64 fp32
// accumulators in registers, per-thread input vector in padded shared
// (stride 65 -> conflict-free dynamic indexing).
// ---------------------------------------------------------------------------
#define NODE_TPB 128
// dyn smem floats: 3*4096 weights + 64 bias + NODE_TPB*65 input
#define NODE_SMEM_FLOATS (3 * 4096 + 64 + NODE_TPB * 65)

__global__ void __launch_bounds__(NODE_TPB)
k_node(const float* __restrict__ x, const float* __restrict__ Wenc,
       const float* __restrict__ benc, const float* __restrict__ W1, int N) {
    extern __shared__ float sm[];
    float* sWe = sm;                  // 4096
    float* sWa = sm + 4096;           // 4096
    float* sWb = sm + 8192;           // 4096
    float* sB  = sm + 12288;          // 64
    float* sIn = sm + 12352;          // NODE_TPB*65

    int tid = threadIdx.x;
    for (int i = tid; i < 4096; i += NODE_TPB) {
        sWe[i] = Wenc[i];
        sWa[i] = W1[i];
        sWb[i] = W1[4096 + i];
    }
    if (tid < 64) sB[tid] = benc[tid];
    __syncthreads();

    int node = blockIdx.x * NODE_TPB + tid;
    if (node >= N) return;

    const float4* x4 = (const float4*)x;
    const float4* a4 = (const float4*)g_agg;
    int toff = tid * 65;

#pragma unroll
    for (int c = 0; c < 16; c++) {
        float4 xv = x4[(long long)node * 16 + c];
        float4 av = a4[(long long)node * 16 + c];
        sIn[toff + 4 * c + 0] = xv.x + av.x;
        sIn[toff + 4 * c + 1] = xv.y + av.y;
        sIn[toff + 4 * c + 2] = xv.z + av.z;
        sIn[toff + 4 * c + 3] = xv.w + av.w;
    }

    float acc[64];

    // --- emb = relu(in @ W_enc + b_enc) ---
#pragma unroll
    for (int j = 0; j < 64; j++) acc[j] = 0.f;
#pragma unroll 8
    for (int k = 0; k < 64; k++) {
        float a = sIn[toff + k];
        const float4* w = (const float4*)(sWe + k * 64);
#pragma unroll
        for (int j = 0; j < 16; j++) {
            float4 wv = w[j];
            acc[4 * j + 0] += a * wv.x;
            acc[4 * j + 1] += a * wv.y;
            acc[4 * j + 2] += a * wv.z;
            acc[4 * j + 3] += a * wv.w;
        }
    }
#pragma unroll
    for (int j = 0; j < 64; j++) sIn[toff + j] = fmaxf(acc[j] + sB[j], 0.f);

    // --- P = emb @ W1a ---
#pragma unroll
    for (int j = 0; j < 64; j++) acc[j] = 0.f;
#pragma unroll 8
    for (int k = 0; k < 64; k++) {
        float a = sIn[toff + k];
        const float4* w = (const float4*)(sWa + k * 64);
#pragma unroll
        for (int j = 0; j < 16; j++) {
            float4 wv = w[j];
            acc[4 * j + 0] += a * wv.x;
            acc[4 * j + 1] += a * wv.y;
            acc[4 * j + 2] += a * wv.z;
            acc[4 * j + 3] += a * wv.w;
        }
    }
    {
        float4* P4 = (float4*)g_P;
#pragma unroll
        for (int j = 0; j < 16; j++)
            P4[(long long)node * 16 + j] =
                make_float4(acc[4 * j + 0], acc[4 * j + 1], acc[4 * j + 2], acc[4 * j + 3]);
    }

    // --- Q = emb @ W1b ---
#pragma unroll
    for (int j = 0; j < 64; j++) acc[j] = 0.f;
#pragma unroll 8
    for (int k = 0; k < 64; k++) {
        float a = sIn[toff + k];
        const float4* w = (const float4*)(sWb + k * 64);
#pragma unroll
        for (int j = 0; j < 16; j++) {
            float4 wv = w[j];
            acc[4 * j + 0] += a * wv.x;
            acc[4 * j + 1] += a * wv.y;
            acc[4 * j + 2] += a * wv.z;
            acc[4 * j + 3] += a * wv.w;
        }
    }
    {
        float4* Q4 = (float4*)g_Q;
#pragma unroll
        for (int j = 0; j < 16; j++)
            Q4[(long long)node * 16 + j] =
                make_float4(acc[4 * j + 0], acc[4 * j + 1], acc[4 * j + 2], acc[4 * j + 3]);
    }
}

// ---------------------------------------------------------------------------
// Edge kernel: warp per edge.
//   h = relu(P[src] + Q[dst] + b1);  out[e] = h . W2 + b2
// Each lane owns 2 channels (float2): coalesced 256B row gathers from
// L2-resident P/Q, then butterfly reduce.
// ---------------------------------------------------------------------------
__global__ void k_edge(const void* __restrict__ ei,
                       const float* __restrict__ b1, const float* __restrict__ W2,
                       const float* __restrict__ b2, float* __restrict__ out, int E) {
    int t = blockIdx.x * blockDim.x + threadIdx.x;
    int warp = t >> 5;
    int lane = t & 31;
    if (warp >= E) return;

    long long src = edge_at(ei, warp);
    long long dst = edge_at(ei, (long long)E + warp);

    float2 p = ((const float2*)g_P)[src * 32 + lane];
    float2 q = ((const float2*)g_Q)[dst * 32 + lane];
    float2 bb = ((const float2*)b1)[lane];
    float2 w  = ((const float2*)W2)[lane];

    float hx = fmaxf(p.x + q.x + bb.x, 0.f);
    float hy = fmaxf(p.y + q.y + bb.y, 0.f);
    float s = hx * w.x + hy * w.y;

#pragma unroll
    for (int o = 16; o > 0; o >>= 1) s += __shfl_xor_sync(0xFFFFFFFFu, s, o);

    if (lane == 0) out[warp] = s + b2[0];
}

// ---------------------------------------------------------------------------
extern "C" void kernel_launch(void* const* d_in, const int* in_sizes, int n_in,
                              void* d_out, int out_size) {
    const float* x    = (const float*)d_in[0];
    const void*  ei   = d_in[1];
    const float* Wenc = (const float*)d_in[2];
    const float* benc = (const float*)d_in[3];
    const float* W1   = (const float*)d_in[4];
    const float* b1   = (const float*)d_in[5];
    const float* W2   = (const float*)d_in[6];
    const float* b2   = (const float*)d_in[7];
    float* out = (float*)d_out;

    int N = in_sizes[0] / DD;          // 50000
    int E = in_sizes[1] / 2;           // 800000 (element count same for i32/i64)

    // dtype probe
    k_detect<<<1, 32>>>((const int*)ei);

    // zero agg
    int n4 = N * DD / 4;
    k_zero<<<(n4 + 255) / 256, 256>>>(n4);

    // scatter-add x[src] into agg[dst]
    {
        long long warps = ((long long)E + 1) / 2;
        long long threads = warps * 32;
        int blocks = (int)((threads + 255) / 256);
        k_scatter<<<blocks, 256>>>(x, ei, E);
    }

    // node GEMMs (emb, P, Q)
    {
        static int smem_set = -1;
        int smem_bytes = NODE_SMEM_FLOATS * (int)sizeof(float);
        cudaFuncSetAttribute(k_node, cudaFuncAttributeMaxDynamicSharedMemorySize, smem_bytes);
        (void)smem_set;
        int blocks = (N + NODE_TPB - 1) / NODE_TPB;
        k_node<<<blocks, NODE_TPB, smem_bytes>>>(x, Wenc, benc, W1, N);
    }

    // per-edge MLP
    {
        long long threads = (long long)E * 32;
        int blocks = (int)((threads + 255) / 256);
        k_edge<<<blocks, 256>>>(ei, b1, W2, b2, out, E);
    }
}